// round 15
// baseline (speedup 1.0000x reference)
#include <cuda_runtime.h>

// DropBlock: x [64,256,64,64] f32, u [58,58] f32. BLOCK_SIZE=7, DROP_PROB=0.1
// Mask is ~99.4% zeros. Single gated store pass:
//  - 64B (4 float4) per thread; one 4-byte keep-flag load gates all 4 stores
//  - multipliers/x loaded only on kept columns (~0.6%)
// k1 (ballot bitboards -> mult table + keep flags) --PDL--> k2.

#define H 64
#define W 64
#define HW 4096
#define US 58           // H - BS + 1
#define BS 7
#define DROP_PROB 0.1f
#define K2_THREADS 256

typedef unsigned long long u64;

__device__ __align__(16) float d_mult[HW];            // 1024 float4 multipliers
__device__ __align__(4)  unsigned char d_keep8[1024]; // 1 = column kept

// ---------------- Kernel 1: mask via warp ballots ----------------
__global__ __launch_bounds__(1024)
void build_mask_kernel(const float* __restrict__ u) {
    cudaTriggerProgrammaticLaunchCompletion();

    __shared__ u64 s_hdil[US];
    __shared__ u64 s_vdil[H];
    __shared__ int s_sum;

    int tid  = threadIdx.x;
    int lane = tid & 31;
    int warp = tid >> 5;
    if (tid == 0) s_sum = 0;

    int rowA = warp;          // always < 58
    int rowB = warp + 32;     // valid if < 58
    const float* rA = u + rowA * US;

    float a0 = rA[lane];
    float a1 = (lane + 32 < US) ? rA[lane + 32] : 1.0f;
    float b0 = 1.0f, b1 = 1.0f;
    if (rowB < US) {
        const float* rB = u + rowB * US;
        b0 = rB[lane];
        b1 = (lane + 32 < US) ? rB[lane + 32] : 1.0f;
    }

    {
        unsigned m0 = __ballot_sync(0xFFFFFFFFu, a0 < DROP_PROB);
        unsigned m1 = __ballot_sync(0xFFFFFFFFu, a1 < DROP_PROB);
        u64 b = (u64)m0 | ((u64)m1 << 32);
        u64 h = b;
        #pragma unroll
        for (int s = 1; s < BS; s++) h |= b << s;
        if (lane == 0) s_hdil[rowA] = h;
    }
    {
        unsigned m0 = __ballot_sync(0xFFFFFFFFu, b0 < DROP_PROB);
        unsigned m1 = __ballot_sync(0xFFFFFFFFu, b1 < DROP_PROB);
        if (rowB < US && lane == 0) {
            u64 b = (u64)m0 | ((u64)m1 << 32);
            u64 h = b;
            #pragma unroll
            for (int s = 1; s < BS; s++) h |= b << s;
            s_hdil[rowB] = h;
        }
    }
    __syncthreads();

    if (tid < H) {
        int i0 = tid - (BS - 1); if (i0 < 0) i0 = 0;
        int i1 = tid;            if (i1 > US - 1) i1 = US - 1;
        u64 v = 0ULL;
        for (int i = i0; i <= i1; i++) v |= s_hdil[i];
        s_vdil[tid] = v;
        int keep = W - __popcll(v);
        #pragma unroll
        for (int off = 16; off > 0; off >>= 1)
            keep += __shfl_down_sync(0xFFFFFFFFu, keep, off);
        if (lane == 0) atomicAdd(&s_sum, keep);
    }
    __syncthreads();

    float scale = (float)HW / (float)s_sum;

    int q = tid;                 // float4 column q
    int y = q >> 4;
    int x = (q & 15) * 4;
    u64 v = s_vdil[y];
    unsigned dropped4 = (unsigned)((v >> x) & 0xFULL);
    float4 f;
    f.x = (dropped4 & 1u) ? 0.0f : scale;
    f.y = (dropped4 & 2u) ? 0.0f : scale;
    f.z = (dropped4 & 4u) ? 0.0f : scale;
    f.w = (dropped4 & 8u) ? 0.0f : scale;
    reinterpret_cast<float4*>(d_mult)[q] = f;
    d_keep8[q] = (dropped4 != 0xFu) ? 1 : 0;
}

// ---------------- Kernel 2: gated 64B store stream (PDL consumer) --------
// Thread owns 4 consecutive float4s (columns q0..q0+3, q0 % 4 == 0).
// One 4-byte keep-flag load gates all 4; load mult/x only if any kept.
__global__ __launch_bounds__(K2_THREADS)
void apply_mask_kernel(const float4* __restrict__ x4,
                       float4* __restrict__ out4) {
    int t  = blockIdx.x * K2_THREADS + threadIdx.x;
    int i0 = t << 2;                   // float4 index, multiple of 4

    cudaGridDependencySynchronize();   // d_mult / d_keep8 visible

    int q0 = i0 & 1023;                // q0 % 4 == 0
    unsigned kk = *reinterpret_cast<const unsigned*>(&d_keep8[q0]);

    float4 r0 = make_float4(0.f, 0.f, 0.f, 0.f);
    float4 r1 = r0, r2 = r0, r3 = r0;
    if (kk != 0u) {
        const float4* m4 = reinterpret_cast<const float4*>(d_mult);
        float4 m0 = __ldg(&m4[q0]);
        float4 m1 = __ldg(&m4[q0 + 1]);
        float4 m2 = __ldg(&m4[q0 + 2]);
        float4 m3 = __ldg(&m4[q0 + 3]);
        float4 v0 = x4[i0];
        float4 v1 = x4[i0 + 1];
        float4 v2 = x4[i0 + 2];
        float4 v3 = x4[i0 + 3];
        r0.x = v0.x * m0.x; r0.y = v0.y * m0.y; r0.z = v0.z * m0.z; r0.w = v0.w * m0.w;
        r1.x = v1.x * m1.x; r1.y = v1.y * m1.y; r1.z = v1.z * m1.z; r1.w = v1.w * m1.w;
        r2.x = v2.x * m2.x; r2.y = v2.y * m2.y; r2.z = v2.z * m2.z; r2.w = v2.w * m2.w;
        r3.x = v3.x * m3.x; r3.y = v3.y * m3.y; r3.z = v3.z * m3.z; r3.w = v3.w * m3.w;
    }
    out4[i0]     = r0;
    out4[i0 + 1] = r1;
    out4[i0 + 2] = r2;
    out4[i0 + 3] = r3;
}

// Guarded fallback (sizes not divisible by 4*K2_THREADS float4s).
__global__ __launch_bounds__(K2_THREADS)
void apply_mask_kernel_guard(const float4* __restrict__ x4,
                             float4* __restrict__ out4, int n4) {
    int idx = blockIdx.x * K2_THREADS + threadIdx.x;
    cudaGridDependencySynchronize();
    if (idx >= n4) return;
    int q = idx & 1023;
    float4 r = make_float4(0.f, 0.f, 0.f, 0.f);
    if (d_keep8[q]) {
        const float4* m4 = reinterpret_cast<const float4*>(d_mult);
        float4 m = __ldg(&m4[q]);
        float4 v = x4[idx];
        r.x = v.x * m.x; r.y = v.y * m.y; r.z = v.z * m.z; r.w = v.w * m.w;
    }
    out4[idx] = r;
}

extern "C" void kernel_launch(void* const* d_in, const int* in_sizes, int n_in,
                              void* d_out, int out_size) {
    const float* x = (const float*)d_in[0];
    const float* u = (const float*)d_in[1];
    float* out = (float*)d_out;

    build_mask_kernel<<<1, 1024>>>(u);

    int n4 = out_size / 4;               // 16,777,216 float4s (2^24)

    cudaLaunchConfig_t cfg = {};
    cfg.blockDim = dim3(K2_THREADS, 1, 1);
    cfg.dynamicSmemBytes = 0;
    cfg.stream = 0;
    cudaLaunchAttribute attr[1];
    attr[0].id = cudaLaunchAttributeProgrammaticStreamSerialization;
    attr[0].val.programmaticStreamSerializationAllowed = 1;
    cfg.attrs = attr;
    cfg.numAttrs = 1;

    if ((n4 % (4 * K2_THREADS)) == 0) {
        cfg.gridDim = dim3(n4 / (4 * K2_THREADS), 1, 1);   // 16384 blocks
        cudaLaunchKernelEx(&cfg, apply_mask_kernel,
                           (const float4*)x, (float4*)out);
    } else {
        cfg.gridDim = dim3((n4 + K2_THREADS - 1) / K2_THREADS, 1, 1);
        cudaLaunchKernelEx(&cfg, apply_mask_kernel_guard,
                           (const float4*)x, (float4*)out, n4);
    }
}

// round 16
// speedup vs baseline: 1.1497x; 1.1497x over previous
#include <cuda_runtime.h>

// DropBlock: x [64,256,64,64] f32, u [58,58] f32. BLOCK_SIZE=7, DROP_PROB=0.1
// Mask is ~99.4% zeros. Single gated store pass:
//  - 1 float4 per thread (perfectly coalesced: full 128B lines per warp-store,
//    no partial sectors / no read-for-ownership)
//  - 1-byte keep flag gates the x read + multiplier load (~0.6% take it)
// k1 (ballot bitboards -> mult table + keep flags) --PDL--> k2.

#define H 64
#define W 64
#define HW 4096
#define US 58           // H - BS + 1
#define BS 7
#define DROP_PROB 0.1f
#define K2_THREADS 256

typedef unsigned long long u64;

__device__ __align__(16) float d_mult[HW];            // 1024 float4 multipliers
__device__ __align__(4)  unsigned char d_keep8[1024]; // 1 = column kept

// ---------------- Kernel 1: mask via warp ballots ----------------
__global__ __launch_bounds__(1024)
void build_mask_kernel(const float* __restrict__ u) {
    cudaTriggerProgrammaticLaunchCompletion();

    __shared__ u64 s_hdil[US];
    __shared__ u64 s_vdil[H];
    __shared__ int s_sum;

    int tid  = threadIdx.x;
    int lane = tid & 31;
    int warp = tid >> 5;
    if (tid == 0) s_sum = 0;

    int rowA = warp;          // always < 58
    int rowB = warp + 32;     // valid if < 58
    const float* rA = u + rowA * US;

    float a0 = rA[lane];
    float a1 = (lane + 32 < US) ? rA[lane + 32] : 1.0f;
    float b0 = 1.0f, b1 = 1.0f;
    if (rowB < US) {
        const float* rB = u + rowB * US;
        b0 = rB[lane];
        b1 = (lane + 32 < US) ? rB[lane + 32] : 1.0f;
    }

    {
        unsigned m0 = __ballot_sync(0xFFFFFFFFu, a0 < DROP_PROB);
        unsigned m1 = __ballot_sync(0xFFFFFFFFu, a1 < DROP_PROB);
        u64 b = (u64)m0 | ((u64)m1 << 32);
        u64 h = b;
        #pragma unroll
        for (int s = 1; s < BS; s++) h |= b << s;
        if (lane == 0) s_hdil[rowA] = h;
    }
    {
        unsigned m0 = __ballot_sync(0xFFFFFFFFu, b0 < DROP_PROB);
        unsigned m1 = __ballot_sync(0xFFFFFFFFu, b1 < DROP_PROB);
        if (rowB < US && lane == 0) {
            u64 b = (u64)m0 | ((u64)m1 << 32);
            u64 h = b;
            #pragma unroll
            for (int s = 1; s < BS; s++) h |= b << s;
            s_hdil[rowB] = h;
        }
    }
    __syncthreads();

    if (tid < H) {
        int i0 = tid - (BS - 1); if (i0 < 0) i0 = 0;
        int i1 = tid;            if (i1 > US - 1) i1 = US - 1;
        u64 v = 0ULL;
        for (int i = i0; i <= i1; i++) v |= s_hdil[i];
        s_vdil[tid] = v;
        int keep = W - __popcll(v);
        #pragma unroll
        for (int off = 16; off > 0; off >>= 1)
            keep += __shfl_down_sync(0xFFFFFFFFu, keep, off);
        if (lane == 0) atomicAdd(&s_sum, keep);
    }
    __syncthreads();

    float scale = (float)HW / (float)s_sum;

    int q = tid;                 // float4 column q
    int y = q >> 4;
    int x = (q & 15) * 4;
    u64 v = s_vdil[y];
    unsigned dropped4 = (unsigned)((v >> x) & 0xFULL);
    float4 f;
    f.x = (dropped4 & 1u) ? 0.0f : scale;
    f.y = (dropped4 & 2u) ? 0.0f : scale;
    f.z = (dropped4 & 4u) ? 0.0f : scale;
    f.w = (dropped4 & 8u) ? 0.0f : scale;
    reinterpret_cast<float4*>(d_mult)[q] = f;
    d_keep8[q] = (dropped4 != 0xFu) ? 1 : 0;
}

// ---------------- Kernel 2: gated coalesced store stream (PDL consumer) ---
// One float4 per thread: warp stores are full 128B lines (no partial sectors).
// Byte keep-flag (L1-hot 1KB table) gates the rare x-read path.
__global__ __launch_bounds__(K2_THREADS)
void apply_mask_kernel(const float4* __restrict__ x4,
                       float4* __restrict__ out4) {
    int idx = blockIdx.x * K2_THREADS + threadIdx.x;

    cudaGridDependencySynchronize();   // d_mult / d_keep8 visible

    int q = idx & 1023;
    unsigned char k = d_keep8[q];

    float4 r = make_float4(0.f, 0.f, 0.f, 0.f);
    if (k) {
        const float4* m4 = reinterpret_cast<const float4*>(d_mult);
        float4 m = __ldg(&m4[q]);
        float4 v = x4[idx];
        r.x = v.x * m.x; r.y = v.y * m.y; r.z = v.z * m.z; r.w = v.w * m.w;
    }
    out4[idx] = r;
}

// Guarded fallback (odd sizes).
__global__ __launch_bounds__(K2_THREADS)
void apply_mask_kernel_guard(const float4* __restrict__ x4,
                             float4* __restrict__ out4, int n4) {
    int idx = blockIdx.x * K2_THREADS + threadIdx.x;
    cudaGridDependencySynchronize();
    if (idx >= n4) return;
    int q = idx & 1023;
    float4 r = make_float4(0.f, 0.f, 0.f, 0.f);
    if (d_keep8[q]) {
        const float4* m4 = reinterpret_cast<const float4*>(d_mult);
        float4 m = __ldg(&m4[q]);
        float4 v = x4[idx];
        r.x = v.x * m.x; r.y = v.y * m.y; r.z = v.z * m.z; r.w = v.w * m.w;
    }
    out4[idx] = r;
}

extern "C" void kernel_launch(void* const* d_in, const int* in_sizes, int n_in,
                              void* d_out, int out_size) {
    const float* x = (const float*)d_in[0];
    const float* u = (const float*)d_in[1];
    float* out = (float*)d_out;

    build_mask_kernel<<<1, 1024>>>(u);

    int n4 = out_size / 4;               // 16,777,216 float4s (2^24)

    cudaLaunchConfig_t cfg = {};
    cfg.blockDim = dim3(K2_THREADS, 1, 1);
    cfg.dynamicSmemBytes = 0;
    cfg.stream = 0;
    cudaLaunchAttribute attr[1];
    attr[0].id = cudaLaunchAttributeProgrammaticStreamSerialization;
    attr[0].val.programmaticStreamSerializationAllowed = 1;
    cfg.attrs = attr;
    cfg.numAttrs = 1;

    if ((n4 % K2_THREADS) == 0) {
        cfg.gridDim = dim3(n4 / K2_THREADS, 1, 1);   // 65536 blocks
        cudaLaunchKernelEx(&cfg, apply_mask_kernel,
                           (const float4*)x, (float4*)out);
    } else {
        cfg.gridDim = dim3((n4 + K2_THREADS - 1) / K2_THREADS, 1, 1);
        cudaLaunchKernelEx(&cfg, apply_mask_kernel_guard,
                           (const float4*)x, (float4*)out, n4);
    }
}